// round 6
// baseline (speedup 1.0000x reference)
#include <cuda_runtime.h>
#include <cuda_fp16.h>
#include <math.h>

// Problem constants
#define Nn   100000
#define Tt   64
#define Hh   64
#define Gg   256          // 4*H
#define Ee   1000000
#define ETOT (Ee + Nn)    // edges + self loops
#define NB   16           // nodes per LSTM block
#define HW   36           // hsh row stride in 32-bit words (16 fp16x2 pairs + pad)
#define HS   (NB * HW)    // one h buffer in words

// -------- scratch (device globals; no allocations allowed) ----------
__device__ float g_h[Nn * Hh];       // LSTM final hidden
__device__ float g_xh[Nn * 128];     // GAT transformed features [N, heads*H]
__device__ float g_asrc[Nn * 2];
__device__ float g_adst[Nn * 2];
__device__ float g_z[Nn * 2];        // segment sum
__device__ float g_acc[Nn * 128];    // weighted message accumulator
__device__ int   g_estride;          // 1 if edge_index is int32, 2 if int64
__device__ int   g_eoff;             // offset (in int32 words) of dst row

// ==================== edge dtype probe =============================
__global__ void detect_kernel(const int* __restrict__ ei32)
{
    if (threadIdx.x == 0 && blockIdx.x == 0) {
        bool all0 = true;
        #pragma unroll
        for (int i = 1; i < 64; i += 2) all0 &= (ei32[i] == 0);
        g_estride = all0 ? 2 : 1;
        g_eoff    = all0 ? 2 * Ee : Ee;
    }
}

// ==================== helpers ======================================
__device__ __forceinline__ float fast_tanh(float x)
{
    float y;
    asm("tanh.approx.f32 %0, %1;" : "=f"(y) : "f"(x));
    return y;
}
__device__ __forceinline__ float fast_sigmoid(float x)
{
    return fmaf(0.5f, fast_tanh(0.5f * x), 0.5f);
}

// pack two floats into one fp16x2 word (lo, hi) — single cvt instruction
__device__ __forceinline__ unsigned pack2(float lo, float hi)
{
    unsigned u;
    asm("cvt.rn.f16x2.f32 %0, %1, %2;" : "=r"(u) : "f"(hi), "f"(lo));
    return u;
}
__device__ __forceinline__ unsigned tanh2(unsigned x)
{
    unsigned y;
    asm("tanh.approx.f16x2 %0, %1;" : "=r"(y) : "r"(x));
    return y;
}
__device__ __forceinline__ __half2 u2h(unsigned u) { return *reinterpret_cast<__half2*>(&u); }
__device__ __forceinline__ unsigned h2u(__half2 h) { return *reinterpret_cast<unsigned*>(&h); }

// fp16x2 sigmoid: 0.5 + 0.5*tanh(0.5*x)
__device__ __forceinline__ __half2 sig2(unsigned u, __half2 half05)
{
    __half2 x = __hmul2(u2h(u), half05);
    return __hfma2(u2h(tanh2(h2u(x))), half05, half05);
}

// pack two floats into fp16x2 (rn)
__device__ __forceinline__ unsigned f2h2u(float a, float b)
{
    __half2 h = __floats2half2_rn(a, b);
    return *reinterpret_cast<unsigned*>(&h);
}

__device__ __forceinline__ void mma_f16(float& c0, float& c1, float& c2, float& c3,
                                        unsigned a0, unsigned a1, unsigned a2, unsigned a3,
                                        unsigned b0, unsigned b1)
{
    asm("mma.sync.aligned.m16n8k16.row.col.f32.f16.f16.f32 "
        "{%0,%1,%2,%3}, {%4,%5,%6,%7}, {%8,%9}, {%0,%1,%2,%3};"
        : "+f"(c0), "+f"(c1), "+f"(c2), "+f"(c3)
        : "r"(a0), "r"(a1), "r"(a2), "r"(a3), "r"(b0), "r"(b1));
}

// ==================== LSTM (fused tensor-core step) ================
// 256 threads = 8 warps, 16 nodes/block. Warp w owns output dims
// j in [8w, 8w+8) for ALL FOUR gate types: n-tiles at q*64 + 8w.
// C fragments hold i,f,g,o for the same (node,j) in the same thread
// -> cell update in registers. h double-buffered in smem: ONE
// __syncthreads per step.
__global__ void __launch_bounds__(256, 2)
lstm_kernel(const float* __restrict__ x, const float* __restrict__ w_ih,
            const float* __restrict__ w_hh, const float* __restrict__ b_ih,
            const float* __restrict__ b_hh)
{
    __shared__ float    xsh[Tt * NB * 2];   // x tile [t][n][d]
    __shared__ unsigned hsh[2 * HS];        // double-buffered h, fp16x2 words

    const int tid  = threadIdx.x;
    const int base = blockIdx.x * NB;
    const int wid  = tid >> 5, lane = tid & 31;
    const int grp  = lane >> 2, tig = lane & 3;   // mma groupID / threadInGroup

    // x tile: xsh[t][n][d]
    for (int i = tid; i < NB * Tt * 2; i += 256) {
        int n = i >> 7;       // /128
        int r = i & 127;      // = t*2 + d
        xsh[(r >> 1) * (NB * 2) + n * 2 + (r & 1)] = x[(size_t)(base + n) * 128 + r];
    }
    for (int i = tid; i < 2 * HS; i += 256) hsh[i] = 0u;

    // This thread's gate dims: j0 = 8w + 2*tig, j0+1 ; gate types q=0..3
    const int j0 = wid * 8 + 2 * tig;

    // Per-thread step-invariant constants: bias, w_ih for 8 gate dims
    float bias[4][2], wa[4][2], wb[4][2];
    #pragma unroll
    for (int q = 0; q < 4; ++q) {
        #pragma unroll
        for (int jc = 0; jc < 2; ++jc) {
            int g = q * 64 + j0 + jc;
            bias[q][jc] = b_ih[g] + b_hh[g];
            wa[q][jc]   = w_ih[g * 2];
            wb[q][jc]   = w_ih[g * 2 + 1];
        }
    }

    // Preload B fragments (fp16): B[k][n] = W_hh[g][k], n-col g = q*64+8w+grp.
    unsigned bf[4][4][2];
    #pragma unroll
    for (int q = 0; q < 4; ++q) {
        const float* wr = &w_hh[(size_t)(q * 64 + wid * 8 + grp) * 64];
        #pragma unroll
        for (int kt = 0; kt < 4; ++kt) {
            int k = kt * 16 + 2 * tig;
            bf[q][kt][0] = f2h2u(wr[k],     wr[k + 1]);
            bf[q][kt][1] = f2h2u(wr[k + 8], wr[k + 9]);
        }
    }

    // step-invariant word offsets within a buffer
    const int rp0 = grp * HW + tig;              // A row grp
    const int rp1 = (grp + 8) * HW + tig;        // A row grp+8
    const int sp0 = grp * HW + wid * 4 + tig;    // h store row grp
    const int sp1 = (grp + 8) * HW + wid * 4 + tig;

    const __half2 half05 = __float2half2_rn(0.5f);
    float creg[4] = {0.f, 0.f, 0.f, 0.f};

    __syncthreads();

    for (int t = 0; t < Tt; ++t) {
        const unsigned* rb = &hsh[(t & 1) * HS];         // read buffer
        unsigned*       wbuf = &hsh[((t + 1) & 1) * HS]; // write buffer

        // ---- init accumulators: bias + x W_ih^T (exact fp32) ------
        float2 xg  = *(const float2*)&xsh[t * (NB * 2) + grp * 2];
        float2 xg8 = *(const float2*)&xsh[t * (NB * 2) + (grp + 8) * 2];
        float c[4][4];
        #pragma unroll
        for (int q = 0; q < 4; ++q) {
            c[q][0] = fmaf(wb[q][0], xg.y,  fmaf(wa[q][0], xg.x,  bias[q][0]));
            c[q][1] = fmaf(wb[q][1], xg.y,  fmaf(wa[q][1], xg.x,  bias[q][1]));
            c[q][2] = fmaf(wb[q][0], xg8.y, fmaf(wa[q][0], xg8.x, bias[q][0]));
            c[q][3] = fmaf(wb[q][1], xg8.y, fmaf(wa[q][1], xg8.x, bias[q][1]));
        }
        // ---- tensor-core h @ W_hh^T over K = 64 (4 k16 tiles) -----
        #pragma unroll
        for (int kt = 0; kt < 4; ++kt) {
            unsigned a0 = rb[rp0 + kt * 8];
            unsigned a1 = rb[rp1 + kt * 8];
            unsigned a2 = rb[rp0 + kt * 8 + 4];
            unsigned a3 = rb[rp1 + kt * 8 + 4];
            #pragma unroll
            for (int q = 0; q < 4; ++q)
                mma_f16(c[q][0], c[q][1], c[q][2], c[q][3],
                        a0, a1, a2, a3, bf[q][kt][0], bf[q][kt][1]);
        }

        // ---- cell update: fp16x2 activations, fp32 c-state --------
        #pragma unroll
        for (int pb = 0; pb < 4; pb += 2) {       // pair (pb, pb+1)
            __half2 i2 = sig2(pack2(c[0][pb], c[0][pb + 1]), half05);
            __half2 f2 = sig2(pack2(c[1][pb], c[1][pb + 1]), half05);
            __half2 g2 = u2h(tanh2(pack2(c[2][pb], c[2][pb + 1])));
            float cc0 = fmaf(__low2float(f2),  creg[pb],
                             __low2float(i2)  * __low2float(g2));
            float cc1 = fmaf(__high2float(f2), creg[pb + 1],
                             __high2float(i2) * __high2float(g2));
            creg[pb]     = cc0;
            creg[pb + 1] = cc1;
            if (t == Tt - 1) {
                // final step in fp32 for full-precision g_h
                float og0 = fast_sigmoid(c[3][pb]);
                float og1 = fast_sigmoid(c[3][pb + 1]);
                float h0 = og0 * fast_tanh(cc0);
                float h1 = og1 * fast_tanh(cc1);
                int row = (pb == 0) ? grp : grp + 8;
                *(float2*)&g_h[(size_t)(base + row) * 64 + j0] = make_float2(h0, h1);
            } else {
                __half2 o2 = sig2(pack2(c[3][pb], c[3][pb + 1]), half05);
                __half2 hh = __hmul2(o2, u2h(tanh2(pack2(cc0, cc1))));
                wbuf[(pb == 0) ? sp0 : sp1] = h2u(hh);
            }
        }
        __syncthreads();   // writes visible before next step's reads
    }
}

// ==================== GAT: feature transform =======================
__global__ void __launch_bounds__(256)
xform_kernel(const float* __restrict__ gat_w)
{
    __shared__ float gwt[64 * 128];   // gat_w transposed [k][hg]
    __shared__ float hs[16 * 64];     // 16 nodes
    const int tid  = threadIdx.x;
    const int base = blockIdx.x * 16;

    for (int i = tid; i < 128 * 64; i += 256) {
        int hg = i >> 6, k = i & 63;
        gwt[k * 128 + hg] = gat_w[i];
    }
    for (int i = tid; i < 16 * 64; i += 256) hs[i] = g_h[(size_t)base * 64 + i];
    __syncthreads();

    const int hg = tid & 127, ng = tid >> 7;   // ng in {0,1} -> 8 nodes
    float acc[8] = {0, 0, 0, 0, 0, 0, 0, 0};
    #pragma unroll 8
    for (int k = 0; k < 64; ++k) {
        float w = gwt[k * 128 + hg];
        #pragma unroll
        for (int i = 0; i < 8; ++i) acc[i] += hs[(ng * 8 + i) * 64 + k] * w;
    }
    #pragma unroll
    for (int i = 0; i < 8; ++i) {
        size_t n = base + ng * 8 + i;
        g_xh[n * 128 + hg] = acc[i];
        g_acc[n * 128 + hg] = 0.f;
    }
}

// ==================== GAT: attention coefficients ==================
__global__ void __launch_bounds__(256)
attn_kernel(const float* __restrict__ att_src, const float* __restrict__ att_dst)
{
    int wid  = (blockIdx.x * 256 + threadIdx.x) >> 5;
    int lane = threadIdx.x & 31;
    if (wid >= Nn) return;
    float4 xv = *(const float4*)&g_xh[(size_t)wid * 128 + lane * 4];
    float4 as = *(const float4*)&att_src[lane * 4];
    float4 ad = *(const float4*)&att_dst[lane * 4];
    float ps = xv.x * as.x + xv.y * as.y + xv.z * as.z + xv.w * as.w;
    float pd = xv.x * ad.x + xv.y * ad.y + xv.z * ad.z + xv.w * ad.w;
    #pragma unroll
    for (int off = 8; off; off >>= 1) {
        ps += __shfl_down_sync(0xffffffffu, ps, off, 16);
        pd += __shfl_down_sync(0xffffffffu, pd, off, 16);
    }
    if ((lane & 15) == 0) {
        int h = lane >> 4;
        g_asrc[wid * 2 + h] = ps;
        g_adst[wid * 2 + h] = pd;
        g_z[wid * 2 + h]    = 0.f;
    }
}

// ==================== GAT: exp-sum + weighted messages =============
// Attention logits are O(0.05): softmax without max-subtraction is
// mathematically identical and numerically safe -> no max pass.
__global__ void __launch_bounds__(256)
edge_sum_kernel(const int* __restrict__ ei32)
{
    int w    = (blockIdx.x * 256 + threadIdx.x) >> 5;
    int lane = threadIdx.x & 31;
    if (w >= ETOT) return;
    const int st = g_estride, of = g_eoff;
    int s, d;
    if (w < Ee) { s = ei32[(size_t)w * st]; d = ei32[(size_t)of + (size_t)w * st]; }
    else        { s = d = w - Ee; }
    float e0 = g_asrc[s * 2]     + g_adst[d * 2];
    float e1 = g_asrc[s * 2 + 1] + g_adst[d * 2 + 1];
    e0 = e0 > 0.f ? e0 : 0.2f * e0;
    e1 = e1 > 0.f ? e1 : 0.2f * e1;
    float w0 = __expf(e0);
    float w1 = __expf(e1);
    if (lane == 0) {
        atomicAdd(&g_z[d * 2],     w0);
        atomicAdd(&g_z[d * 2 + 1], w1);
    }
    const float* xs = &g_xh[(size_t)s * 128];
    float* ac = &g_acc[(size_t)d * 128];
    #pragma unroll
    for (int r = 0; r < 4; ++r) {
        int hg = lane + 32 * r;
        float coef = (hg < 64) ? w0 : w1;
        atomicAdd(&ac[hg], coef * xs[hg]);
    }
}

// ==================== finalize: mean heads + relu + linear + sigmoid
__global__ void __launch_bounds__(256)
final_kernel(const float* __restrict__ gat_b, const float* __restrict__ lin_w,
             const float* __restrict__ lin_b, float* __restrict__ out)
{
    int n    = (blockIdx.x * 256 + threadIdx.x) >> 5;
    int lane = threadIdx.x & 31;
    if (n >= Nn) return;
    float r0 = 0.5f / g_z[n * 2];
    float r1 = 0.5f / g_z[n * 2 + 1];
    float y0 = 0.f, y1 = 0.f;
    const float* ac = &g_acc[(size_t)n * 128];
    #pragma unroll
    for (int r = 0; r < 2; ++r) {
        int dd = lane + 32 * r;
        float v = ac[dd] * r0 + ac[64 + dd] * r1 + gat_b[dd];
        v = v > 0.f ? v : 0.f;
        y0 += v * lin_w[dd];
        y1 += v * lin_w[64 + dd];
    }
    #pragma unroll
    for (int off = 16; off; off >>= 1) {
        y0 += __shfl_down_sync(0xffffffffu, y0, off);
        y1 += __shfl_down_sync(0xffffffffu, y1, off);
    }
    if (lane == 0) {
        out[n * 2]     = 1.f / (1.f + __expf(-(y0 + lin_b[0])));
        out[n * 2 + 1] = 1.f / (1.f + __expf(-(y1 + lin_b[1])));
    }
}

// ==================== launch =======================================
extern "C" void kernel_launch(void* const* d_in, const int* in_sizes, int n_in,
                              void* d_out, int out_size)
{
    const float* x       = (const float*)d_in[0];
    const int*   ei32    = (const int*)d_in[1];     // int32 view; probe decides layout
    const float* w_ih    = (const float*)d_in[2];
    const float* w_hh    = (const float*)d_in[3];
    const float* b_ih    = (const float*)d_in[4];
    const float* b_hh    = (const float*)d_in[5];
    const float* gat_w   = (const float*)d_in[6];
    const float* att_src = (const float*)d_in[7];
    const float* att_dst = (const float*)d_in[8];
    const float* gat_b   = (const float*)d_in[9];
    const float* lin_w   = (const float*)d_in[10];
    const float* lin_b   = (const float*)d_in[11];
    float*       out     = (float*)d_out;

    detect_kernel<<<1, 32>>>(ei32);
    lstm_kernel<<<Nn / NB, 256>>>(x, w_ih, w_hh, b_ih, b_hh);
    xform_kernel<<<Nn / 16, 256>>>(gat_w);
    attn_kernel<<<Nn / 8, 256>>>(att_src, att_dst);
    edge_sum_kernel<<<(ETOT + 7) / 8, 256>>>(ei32);
    final_kernel<<<Nn / 8, 256>>>(gat_b, lin_w, lin_b, out);
}

// round 7
// speedup vs baseline: 1.0636x; 1.0636x over previous
#include <cuda_runtime.h>
#include <cuda_fp16.h>
#include <math.h>

// Problem constants
#define Nn   100000
#define Tt   64
#define Hh   64
#define Gg   256          // 4*H
#define Ee   1000000
#define ETOT (Ee + Nn)    // edges + self loops
#define NB   16           // nodes per LSTM block
#define HW   36           // hsh row stride in 32-bit words (16 fp16x2 pairs + pad)
#define HS   (NB * HW)    // one h buffer in words

// -------- scratch (device globals; no allocations allowed) ----------
__device__ float g_h[Nn * Hh];       // LSTM final hidden
__device__ float g_xh[Nn * 128];     // GAT transformed features [N, heads*H]
__device__ float g_asrc[Nn * 2];
__device__ float g_adst[Nn * 2];
__device__ float g_z[Nn * 2];        // segment sum
__device__ float g_acc[Nn * 128];    // weighted message accumulator
__device__ int   g_estride;          // 1 if edge_index is int32, 2 if int64
__device__ int   g_eoff;             // offset (in int32 words) of dst row

// ==================== edge dtype probe =============================
__global__ void detect_kernel(const int* __restrict__ ei32)
{
    if (threadIdx.x == 0 && blockIdx.x == 0) {
        bool all0 = true;
        #pragma unroll
        for (int i = 1; i < 64; i += 2) all0 &= (ei32[i] == 0);
        g_estride = all0 ? 2 : 1;
        g_eoff    = all0 ? 2 * Ee : Ee;
    }
}

// ==================== helpers ======================================
__device__ __forceinline__ unsigned tanh2(unsigned x)
{
    unsigned y;
    asm("tanh.approx.f16x2 %0, %1;" : "=r"(y) : "r"(x));
    return y;
}
__device__ __forceinline__ __half2 u2h(unsigned u) { return *reinterpret_cast<__half2*>(&u); }
__device__ __forceinline__ unsigned h2u(__half2 h) { return *reinterpret_cast<unsigned*>(&h); }

// fp16x2 sigmoid: 0.5 + 0.5*tanh(0.5*x)
__device__ __forceinline__ __half2 sig2(unsigned u, __half2 half05)
{
    __half2 x = __hmul2(u2h(u), half05);
    return __hfma2(u2h(tanh2(h2u(x))), half05, half05);
}

// pack two floats into fp16x2 (rn)
__device__ __forceinline__ unsigned f2h2u(float a, float b)
{
    __half2 h = __floats2half2_rn(a, b);
    return *reinterpret_cast<unsigned*>(&h);
}

// m16n8k16, fp16 in / fp16 accum. D regs = 2x fp16x2:
//   c0 = (row grp,   cols j0, j0+1),  c1 = (row grp+8, cols j0, j0+1)
__device__ __forceinline__ void mma_f16acc(unsigned& c0, unsigned& c1,
                                           unsigned a0, unsigned a1, unsigned a2, unsigned a3,
                                           unsigned b0, unsigned b1)
{
    asm("mma.sync.aligned.m16n8k16.row.col.f16.f16.f16.f16 "
        "{%0,%1}, {%2,%3,%4,%5}, {%6,%7}, {%0,%1};"
        : "+r"(c0), "+r"(c1)
        : "r"(a0), "r"(a1), "r"(a2), "r"(a3), "r"(b0), "r"(b1));
}

// ==================== LSTM (all-fp16 fused step) ===================
// 256 threads = 8 warps, 16 nodes/block. Warp w owns output dims
// j in [8w, 8w+8) for all four gates (n-tiles q*64+8w). fp16
// accumulators arrive pre-packed -> activations run on fp16x2 with
// ZERO conversions in the steady-state loop. h double-buffered,
// one __syncthreads per step.
__global__ void __launch_bounds__(256, 2)
lstm_kernel(const float* __restrict__ x, const float* __restrict__ w_ih,
            const float* __restrict__ w_hh, const float* __restrict__ b_ih,
            const float* __restrict__ b_hh)
{
    __shared__ unsigned xsh[Tt * NB * 2];   // broadcast half2 per (t, n, d)
    __shared__ unsigned hsh[2 * HS];        // double-buffered h, fp16x2 words

    const int tid  = threadIdx.x;
    const int base = blockIdx.x * NB;
    const int wid  = tid >> 5, lane = tid & 31;
    const int grp  = lane >> 2, tig = lane & 3;   // mma groupID / threadInGroup

    // x tile: xsh[t][n][d] = half2(x, x)  (broadcast-packed once)
    for (int i = tid; i < NB * Tt * 2; i += 256) {
        int n = i >> 7;       // /128
        int r = i & 127;      // = t*2 + d
        float v = x[(size_t)(base + n) * 128 + r];
        xsh[(r >> 1) * (NB * 2) + n * 2 + (r & 1)] = h2u(__float2half2_rn(v));
    }
    for (int i = tid; i < 2 * HS; i += 256) hsh[i] = 0u;

    // This thread's gate dims: j0 = 8w + 2*tig, j0+1 ; gate types q=0..3
    const int j0 = wid * 8 + 2 * tig;

    // Packed step-invariant constants
    unsigned bias2[4], wa2[4], wb2[4];
    #pragma unroll
    for (int q = 0; q < 4; ++q) {
        int g = q * 64 + j0;
        bias2[q] = f2h2u(b_ih[g] + b_hh[g], b_ih[g + 1] + b_hh[g + 1]);
        wa2[q]   = f2h2u(w_ih[g * 2],     w_ih[(g + 1) * 2]);
        wb2[q]   = f2h2u(w_ih[g * 2 + 1], w_ih[(g + 1) * 2 + 1]);
    }

    // Preload B fragments (fp16): B[k][n] = W_hh[g][k], n-col g = q*64+8w+grp.
    unsigned bf[4][4][2];
    #pragma unroll
    for (int q = 0; q < 4; ++q) {
        const float* wr = &w_hh[(size_t)(q * 64 + wid * 8 + grp) * 64];
        #pragma unroll
        for (int kt = 0; kt < 4; ++kt) {
            int k = kt * 16 + 2 * tig;
            bf[q][kt][0] = f2h2u(wr[k],     wr[k + 1]);
            bf[q][kt][1] = f2h2u(wr[k + 8], wr[k + 9]);
        }
    }

    // step-invariant word offsets within a buffer
    const int rp0 = grp * HW + tig;              // A row grp
    const int rp1 = (grp + 8) * HW + tig;        // A row grp+8
    const int sp0 = grp * HW + wid * 4 + tig;    // h store row grp
    const int sp1 = (grp + 8) * HW + wid * 4 + tig;

    const __half2 half05 = __float2half2_rn(0.5f);
    __half2 creg[2] = {__float2half2_rn(0.f), __float2half2_rn(0.f)};

    __syncthreads();

    for (int t = 0; t < Tt; ++t) {
        const unsigned* rb   = &hsh[(t & 1) * HS];        // read buffer
        unsigned*       wbuf = &hsh[((t + 1) & 1) * HS];  // write buffer

        // ---- init accumulators: bias + x W_ih^T (all HFMA2) -------
        unsigned xl0 = xsh[t * (NB * 2) + grp * 2];
        unsigned xh0 = xsh[t * (NB * 2) + grp * 2 + 1];
        unsigned xl1 = xsh[t * (NB * 2) + (grp + 8) * 2];
        unsigned xh1 = xsh[t * (NB * 2) + (grp + 8) * 2 + 1];
        unsigned c[4][2];
        #pragma unroll
        for (int q = 0; q < 4; ++q) {
            c[q][0] = h2u(__hfma2(u2h(wb2[q]), u2h(xh0),
                          __hfma2(u2h(wa2[q]), u2h(xl0), u2h(bias2[q]))));
            c[q][1] = h2u(__hfma2(u2h(wb2[q]), u2h(xh1),
                          __hfma2(u2h(wa2[q]), u2h(xl1), u2h(bias2[q]))));
        }
        // ---- tensor-core h @ W_hh^T over K = 64 (4 k16 tiles) -----
        #pragma unroll
        for (int kt = 0; kt < 4; ++kt) {
            unsigned a0 = rb[rp0 + kt * 8];
            unsigned a1 = rb[rp1 + kt * 8];
            unsigned a2 = rb[rp0 + kt * 8 + 4];
            unsigned a3 = rb[rp1 + kt * 8 + 4];
            #pragma unroll
            for (int q = 0; q < 4; ++q)
                mma_f16acc(c[q][0], c[q][1], a0, a1, a2, a3,
                           bf[q][kt][0], bf[q][kt][1]);
        }

        // ---- cell update: pure fp16x2, zero conversions -----------
        #pragma unroll
        for (int r = 0; r < 2; ++r) {
            __half2 i2 = sig2(c[0][r], half05);
            __half2 f2 = sig2(c[1][r], half05);
            __half2 g2 = u2h(tanh2(c[2][r]));
            __half2 o2 = sig2(c[3][r], half05);
            creg[r] = __hfma2(f2, creg[r], __hmul2(i2, g2));
            __half2 hh = __hmul2(o2, u2h(tanh2(h2u(creg[r]))));
            if (t == Tt - 1) {
                int row = r ? (grp + 8) : grp;
                *(float2*)&g_h[(size_t)(base + row) * 64 + j0] =
                    make_float2(__low2float(hh), __high2float(hh));
            } else {
                wbuf[r ? sp1 : sp0] = h2u(hh);
            }
        }
        __syncthreads();   // writes visible before next step's reads
    }
}

// ==================== GAT: feature transform =======================
__global__ void __launch_bounds__(256)
xform_kernel(const float* __restrict__ gat_w)
{
    __shared__ float gwt[64 * 128];   // gat_w transposed [k][hg]
    __shared__ float hs[16 * 64];     // 16 nodes
    const int tid  = threadIdx.x;
    const int base = blockIdx.x * 16;

    for (int i = tid; i < 128 * 64; i += 256) {
        int hg = i >> 6, k = i & 63;
        gwt[k * 128 + hg] = gat_w[i];
    }
    for (int i = tid; i < 16 * 64; i += 256) hs[i] = g_h[(size_t)base * 64 + i];
    __syncthreads();

    const int hg = tid & 127, ng = tid >> 7;   // ng in {0,1} -> 8 nodes
    float acc[8] = {0, 0, 0, 0, 0, 0, 0, 0};
    #pragma unroll 8
    for (int k = 0; k < 64; ++k) {
        float w = gwt[k * 128 + hg];
        #pragma unroll
        for (int i = 0; i < 8; ++i) acc[i] += hs[(ng * 8 + i) * 64 + k] * w;
    }
    #pragma unroll
    for (int i = 0; i < 8; ++i) {
        size_t n = base + ng * 8 + i;
        g_xh[n * 128 + hg] = acc[i];
        g_acc[n * 128 + hg] = 0.f;
    }
}

// ==================== GAT: attention coefficients ==================
__global__ void __launch_bounds__(256)
attn_kernel(const float* __restrict__ att_src, const float* __restrict__ att_dst)
{
    int wid  = (blockIdx.x * 256 + threadIdx.x) >> 5;
    int lane = threadIdx.x & 31;
    if (wid >= Nn) return;
    float4 xv = *(const float4*)&g_xh[(size_t)wid * 128 + lane * 4];
    float4 as = *(const float4*)&att_src[lane * 4];
    float4 ad = *(const float4*)&att_dst[lane * 4];
    float ps = xv.x * as.x + xv.y * as.y + xv.z * as.z + xv.w * as.w;
    float pd = xv.x * ad.x + xv.y * ad.y + xv.z * ad.z + xv.w * ad.w;
    #pragma unroll
    for (int off = 8; off; off >>= 1) {
        ps += __shfl_down_sync(0xffffffffu, ps, off, 16);
        pd += __shfl_down_sync(0xffffffffu, pd, off, 16);
    }
    if ((lane & 15) == 0) {
        int h = lane >> 4;
        g_asrc[wid * 2 + h] = ps;
        g_adst[wid * 2 + h] = pd;
        g_z[wid * 2 + h]    = 0.f;
    }
}

// ==================== GAT: exp-sum + weighted messages =============
// Attention logits are O(0.05): softmax without max-subtraction is
// mathematically identical and numerically safe -> no max pass.
__global__ void __launch_bounds__(256)
edge_sum_kernel(const int* __restrict__ ei32)
{
    int w    = (blockIdx.x * 256 + threadIdx.x) >> 5;
    int lane = threadIdx.x & 31;
    if (w >= ETOT) return;
    const int st = g_estride, of = g_eoff;
    int s, d;
    if (w < Ee) { s = ei32[(size_t)w * st]; d = ei32[(size_t)of + (size_t)w * st]; }
    else        { s = d = w - Ee; }
    float e0 = g_asrc[s * 2]     + g_adst[d * 2];
    float e1 = g_asrc[s * 2 + 1] + g_adst[d * 2 + 1];
    e0 = e0 > 0.f ? e0 : 0.2f * e0;
    e1 = e1 > 0.f ? e1 : 0.2f * e1;
    float w0 = __expf(e0);
    float w1 = __expf(e1);
    if (lane == 0) {
        atomicAdd(&g_z[d * 2],     w0);
        atomicAdd(&g_z[d * 2 + 1], w1);
    }
    const float* xs = &g_xh[(size_t)s * 128];
    float* ac = &g_acc[(size_t)d * 128];
    #pragma unroll
    for (int r = 0; r < 4; ++r) {
        int hg = lane + 32 * r;
        float coef = (hg < 64) ? w0 : w1;
        atomicAdd(&ac[hg], coef * xs[hg]);
    }
}

// ==================== finalize: mean heads + relu + linear + sigmoid
__global__ void __launch_bounds__(256)
final_kernel(const float* __restrict__ gat_b, const float* __restrict__ lin_w,
             const float* __restrict__ lin_b, float* __restrict__ out)
{
    int n    = (blockIdx.x * 256 + threadIdx.x) >> 5;
    int lane = threadIdx.x & 31;
    if (n >= Nn) return;
    float r0 = 0.5f / g_z[n * 2];
    float r1 = 0.5f / g_z[n * 2 + 1];
    float y0 = 0.f, y1 = 0.f;
    const float* ac = &g_acc[(size_t)n * 128];
    #pragma unroll
    for (int r = 0; r < 2; ++r) {
        int dd = lane + 32 * r;
        float v = ac[dd] * r0 + ac[64 + dd] * r1 + gat_b[dd];
        v = v > 0.f ? v : 0.f;
        y0 += v * lin_w[dd];
        y1 += v * lin_w[64 + dd];
    }
    #pragma unroll
    for (int off = 16; off; off >>= 1) {
        y0 += __shfl_down_sync(0xffffffffu, y0, off);
        y1 += __shfl_down_sync(0xffffffffu, y1, off);
    }
    if (lane == 0) {
        out[n * 2]     = 1.f / (1.f + __expf(-(y0 + lin_b[0])));
        out[n * 2 + 1] = 1.f / (1.f + __expf(-(y1 + lin_b[1])));
    }
}

// ==================== launch =======================================
extern "C" void kernel_launch(void* const* d_in, const int* in_sizes, int n_in,
                              void* d_out, int out_size)
{
    const float* x       = (const float*)d_in[0];
    const int*   ei32    = (const int*)d_in[1];     // int32 view; probe decides layout
    const float* w_ih    = (const float*)d_in[2];
    const float* w_hh    = (const float*)d_in[3];
    const float* b_ih    = (const float*)d_in[4];
    const float* b_hh    = (const float*)d_in[5];
    const float* gat_w   = (const float*)d_in[6];
    const float* att_src = (const float*)d_in[7];
    const float* att_dst = (const float*)d_in[8];
    const float* gat_b   = (const float*)d_in[9];
    const float* lin_w   = (const float*)d_in[10];
    const float* lin_b   = (const float*)d_in[11];
    float*       out     = (float*)d_out;

    detect_kernel<<<1, 32>>>(ei32);
    lstm_kernel<<<Nn / NB, 256>>>(x, w_ih, w_hh, b_ih, b_hh);
    xform_kernel<<<Nn / 16, 256>>>(gat_w);
    attn_kernel<<<Nn / 8, 256>>>(att_src, att_dst);
    edge_sum_kernel<<<(ETOT + 7) / 8, 256>>>(ei32);
    final_kernel<<<Nn / 8, 256>>>(gat_b, lin_w, lin_b, out);
}

// round 9
// speedup vs baseline: 1.1154x; 1.0487x over previous
#include <cuda_runtime.h>
#include <cuda_fp16.h>
#include <math.h>

// Problem constants
#define Nn   100000
#define Tt   64
#define Ee   1000000
#define ETOT (Ee + Nn)    // edges + self loops
#define NB   32           // nodes per LSTM block
#define HW   36           // hsh row stride in 32-bit words
#define HS   (NB * HW)    // one h buffer in words

// -------- scratch (device globals; no allocations allowed) ----------
__device__ float g_h[Nn * 64];       // LSTM final hidden
__device__ float g_xh[Nn * 128];     // GAT transformed features [N, heads*H]
__device__ float g_asrc[Nn * 2];
__device__ float g_adst[Nn * 2];
__device__ float g_z[Nn * 2];        // segment sum
__device__ float g_acc[Nn * 128];    // weighted message accumulator
__device__ int   g_estride;          // 1 if edge_index is int32, 2 if int64
__device__ int   g_eoff;             // offset (in int32 words) of dst row

// ==================== edge dtype probe =============================
__global__ void detect_kernel(const int* __restrict__ ei32)
{
    if (threadIdx.x == 0 && blockIdx.x == 0) {
        bool all0 = true;
        #pragma unroll
        for (int i = 1; i < 64; i += 2) all0 &= (ei32[i] == 0);
        g_estride = all0 ? 2 : 1;
        g_eoff    = all0 ? 2 * Ee : Ee;
    }
}

// ==================== helpers ======================================
__device__ __forceinline__ unsigned tanh2(unsigned x)
{
    unsigned y;
    asm("tanh.approx.f16x2 %0, %1;" : "=r"(y) : "r"(x));
    return y;
}
__device__ __forceinline__ __half2 u2h(unsigned u) { return *reinterpret_cast<__half2*>(&u); }
__device__ __forceinline__ unsigned h2u(__half2 h) { return *reinterpret_cast<unsigned*>(&h); }

// fp16x2 sigmoid: 0.5 + 0.5*tanh(0.5*x)
__device__ __forceinline__ __half2 sig2(unsigned u, __half2 half05)
{
    __half2 x = __hmul2(u2h(u), half05);
    return __hfma2(u2h(tanh2(h2u(x))), half05, half05);
}

__device__ __forceinline__ unsigned f2h2u(float a, float b)
{
    __half2 h = __floats2half2_rn(a, b);
    return *reinterpret_cast<unsigned*>(&h);
}

// m16n8k16, fp16 in / fp16 accum. D regs = 2x fp16x2.
__device__ __forceinline__ void mma_f16acc(unsigned& c0, unsigned& c1,
                                           unsigned a0, unsigned a1, unsigned a2, unsigned a3,
                                           unsigned b0, unsigned b1)
{
    asm("mma.sync.aligned.m16n8k16.row.col.f16.f16.f16.f16 "
        "{%0,%1}, {%2,%3,%4,%5}, {%6,%7}, {%0,%1};"
        : "+r"(c0), "+r"(c1)
        : "r"(a0), "r"(a1), "r"(a2), "r"(a3), "r"(b0), "r"(b1));
}

// ==================== LSTM (all-fp16, 32 nodes/block) ==============
// 256 threads = 8 warps. Warp w owns gate dims j in [8w, 8w+8) for
// all four gates; B fragments live in registers and are reused by
// TWO M-tiles (rows 0-15 and 16-31) -> per-step barrier cost
// amortized over 2x work. fp16 accumulators arrive packed; cell
// update is pure fp16x2; h double-buffered, ONE barrier per step.
__global__ void __launch_bounds__(256, 2)
lstm_kernel(const float* __restrict__ x, const float* __restrict__ w_ih,
            const float* __restrict__ w_hh, const float* __restrict__ b_ih,
            const float* __restrict__ b_hh)
{
    __shared__ unsigned xsh[Tt * NB * 2];   // broadcast half2 per (t, n, d)
    __shared__ unsigned hsh[2 * HS];        // double-buffered h, fp16x2 words

    const int tid  = threadIdx.x;
    const int base = blockIdx.x * NB;
    const int wid  = tid >> 5, lane = tid & 31;
    const int grp  = lane >> 2, tig = lane & 3;   // mma groupID / threadInGroup

    // x tile: xsh[t][n][d] = half2(x, x)  (broadcast-packed once)
    for (int i = tid; i < NB * Tt * 2; i += 256) {
        int n = i >> 7;       // /128  (n in 0..31)
        int r = i & 127;      // = t*2 + d
        float v = x[(size_t)(base + n) * 128 + r];
        xsh[(r >> 1) * (NB * 2) + n * 2 + (r & 1)] = h2u(__float2half2_rn(v));
    }
    for (int i = tid; i < 2 * HS; i += 256) hsh[i] = 0u;

    // This thread's gate dims: j0 = 8w + 2*tig, j0+1 ; gate types q=0..3
    const int j0 = wid * 8 + 2 * tig;

    // Packed step-invariant constants
    unsigned bias2[4], wa2[4], wb2[4];
    #pragma unroll
    for (int q = 0; q < 4; ++q) {
        int g = q * 64 + j0;
        bias2[q] = f2h2u(b_ih[g] + b_hh[g], b_ih[g + 1] + b_hh[g + 1]);
        wa2[q]   = f2h2u(w_ih[g * 2],     w_ih[(g + 1) * 2]);
        wb2[q]   = f2h2u(w_ih[g * 2 + 1], w_ih[(g + 1) * 2 + 1]);
    }

    // Preload B fragments (fp16): B[k][n] = W_hh[g][k], n-col g = q*64+8w+grp.
    unsigned bf[4][4][2];
    #pragma unroll
    for (int q = 0; q < 4; ++q) {
        const float* wr = &w_hh[(size_t)(q * 64 + wid * 8 + grp) * 64];
        #pragma unroll
        for (int kt = 0; kt < 4; ++kt) {
            int k = kt * 16 + 2 * tig;
            bf[q][kt][0] = f2h2u(wr[k],     wr[k + 1]);
            bf[q][kt][1] = f2h2u(wr[k + 8], wr[k + 9]);
        }
    }

    // step-invariant word offsets within a buffer (two M-tiles)
    const int rp[4] = { grp * HW + tig,        (grp + 8) * HW + tig,
                        (grp + 16) * HW + tig, (grp + 24) * HW + tig };
    const int sp[4] = { grp * HW + wid * 4 + tig,        (grp + 8) * HW + wid * 4 + tig,
                        (grp + 16) * HW + wid * 4 + tig, (grp + 24) * HW + wid * 4 + tig };

    const __half2 half05 = __float2half2_rn(0.5f);
    __half2 creg[4];
    #pragma unroll
    for (int r = 0; r < 4; ++r) creg[r] = __float2half2_rn(0.f);

    __syncthreads();

    for (int t = 0; t < Tt; ++t) {
        const unsigned* rb   = &hsh[(t & 1) * HS];        // read buffer
        unsigned*       wbuf = &hsh[((t + 1) & 1) * HS];  // write buffer

        // ---- init accumulators: bias + x W_ih^T (all HFMA2) -------
        unsigned xl[4], xh[4];
        #pragma unroll
        for (int m = 0; m < 4; ++m) {
            int n = grp + 8 * m;
            xl[m] = xsh[t * (NB * 2) + n * 2];
            xh[m] = xsh[t * (NB * 2) + n * 2 + 1];
        }
        unsigned c[4][4];   // [q][row: grp, grp+8, grp+16, grp+24]
        #pragma unroll
        for (int q = 0; q < 4; ++q) {
            #pragma unroll
            for (int m = 0; m < 4; ++m)
                c[q][m] = h2u(__hfma2(u2h(wb2[q]), u2h(xh[m]),
                              __hfma2(u2h(wa2[q]), u2h(xl[m]), u2h(bias2[q]))));
        }
        // ---- tensor-core h @ W_hh^T, two M-tiles, K = 64 ----------
        #pragma unroll
        for (int kt = 0; kt < 4; ++kt) {
            unsigned a0 = rb[rp[0] + kt * 8];
            unsigned a1 = rb[rp[1] + kt * 8];
            unsigned a2 = rb[rp[0] + kt * 8 + 4];
            unsigned a3 = rb[rp[1] + kt * 8 + 4];
            unsigned a4 = rb[rp[2] + kt * 8];
            unsigned a5 = rb[rp[3] + kt * 8];
            unsigned a6 = rb[rp[2] + kt * 8 + 4];
            unsigned a7 = rb[rp[3] + kt * 8 + 4];
            #pragma unroll
            for (int q = 0; q < 4; ++q) {
                mma_f16acc(c[q][0], c[q][1], a0, a1, a2, a3,
                           bf[q][kt][0], bf[q][kt][1]);
                mma_f16acc(c[q][2], c[q][3], a4, a5, a6, a7,
                           bf[q][kt][0], bf[q][kt][1]);
            }
        }

        // ---- cell update: pure fp16x2, zero conversions -----------
        #pragma unroll
        for (int r = 0; r < 4; ++r) {
            __half2 i2 = sig2(c[0][r], half05);
            __half2 f2 = sig2(c[1][r], half05);
            __half2 g2 = u2h(tanh2(c[2][r]));
            __half2 o2 = sig2(c[3][r], half05);
            creg[r] = __hfma2(f2, creg[r], __hmul2(i2, g2));
            __half2 hh = __hmul2(o2, u2h(tanh2(h2u(creg[r]))));
            if (t == Tt - 1) {
                int row = grp + 8 * r;
                *(float2*)&g_h[(size_t)(base + row) * 64 + j0] =
                    make_float2(__low2float(hh), __high2float(hh));
            } else {
                wbuf[sp[r]] = h2u(hh);
            }
        }
        __syncthreads();   // writes visible before next step's reads
    }
}

// ==================== GAT: feature transform =======================
__global__ void __launch_bounds__(256)
xform_kernel(const float* __restrict__ gat_w)
{
    __shared__ float gwt[64 * 128];   // gat_w transposed [k][hg]
    __shared__ float hs[16 * 64];     // 16 nodes
    const int tid  = threadIdx.x;
    const int base = blockIdx.x * 16;

    for (int i = tid; i < 128 * 64; i += 256) {
        int hg = i >> 6, k = i & 63;
        gwt[k * 128 + hg] = gat_w[i];
    }
    for (int i = tid; i < 16 * 64; i += 256) hs[i] = g_h[(size_t)base * 64 + i];
    __syncthreads();

    const int hg = tid & 127, ng = tid >> 7;   // ng in {0,1} -> 8 nodes
    float acc[8] = {0, 0, 0, 0, 0, 0, 0, 0};
    #pragma unroll 8
    for (int k = 0; k < 64; ++k) {
        float w = gwt[k * 128 + hg];
        #pragma unroll
        for (int i = 0; i < 8; ++i) acc[i] += hs[(ng * 8 + i) * 64 + k] * w;
    }
    #pragma unroll
    for (int i = 0; i < 8; ++i) {
        size_t n = base + ng * 8 + i;
        g_xh[n * 128 + hg] = acc[i];
        g_acc[n * 128 + hg] = 0.f;
    }
}

// ==================== GAT: attention coefficients ==================
__global__ void __launch_bounds__(256)
attn_kernel(const float* __restrict__ att_src, const float* __restrict__ att_dst)
{
    int wd   = (blockIdx.x * 256 + threadIdx.x) >> 5;
    int lane = threadIdx.x & 31;
    if (wd >= Nn) return;
    float4 xv = *(const float4*)&g_xh[(size_t)wd * 128 + lane * 4];
    float4 as = *(const float4*)&att_src[lane * 4];
    float4 ad = *(const float4*)&att_dst[lane * 4];
    float ps = xv.x * as.x + xv.y * as.y + xv.z * as.z + xv.w * as.w;
    float pd = xv.x * ad.x + xv.y * ad.y + xv.z * ad.z + xv.w * ad.w;
    #pragma unroll
    for (int off = 8; off; off >>= 1) {
        ps += __shfl_down_sync(0xffffffffu, ps, off, 16);
        pd += __shfl_down_sync(0xffffffffu, pd, off, 16);
    }
    if ((lane & 15) == 0) {
        int h = lane >> 4;
        g_asrc[wd * 2 + h] = ps;
        g_adst[wd * 2 + h] = pd;
        g_z[wd * 2 + h]    = 0.f;
    }
}

// ==================== GAT: exp-sum + weighted messages =============
// Attention logits are O(0.05): softmax without max-subtraction is
// mathematically identical and numerically safe -> no max pass.
__global__ void __launch_bounds__(256)
edge_sum_kernel(const int* __restrict__ ei32)
{
    int w    = (blockIdx.x * 256 + threadIdx.x) >> 5;
    int lane = threadIdx.x & 31;
    if (w >= ETOT) return;
    const int st = g_estride, of = g_eoff;
    int s, d;
    if (w < Ee) { s = ei32[(size_t)w * st]; d = ei32[(size_t)of + (size_t)w * st]; }
    else        { s = d = w - Ee; }
    float e0 = g_asrc[s * 2]     + g_adst[d * 2];
    float e1 = g_asrc[s * 2 + 1] + g_adst[d * 2 + 1];
    e0 = e0 > 0.f ? e0 : 0.2f * e0;
    e1 = e1 > 0.f ? e1 : 0.2f * e1;
    float w0 = __expf(e0);
    float w1 = __expf(e1);
    if (lane == 0) {
        atomicAdd(&g_z[d * 2],     w0);
        atomicAdd(&g_z[d * 2 + 1], w1);
    }
    const float* xs = &g_xh[(size_t)s * 128];
    float* ac = &g_acc[(size_t)d * 128];
    #pragma unroll
    for (int r = 0; r < 4; ++r) {
        int hg = lane + 32 * r;
        float coef = (hg < 64) ? w0 : w1;
        atomicAdd(&ac[hg], coef * xs[hg]);
    }
}

// ==================== finalize: mean heads + relu + linear + sigmoid
__global__ void __launch_bounds__(256)
final_kernel(const float* __restrict__ gat_b, const float* __restrict__ lin_w,
             const float* __restrict__ lin_b, float* __restrict__ out)
{
    int n    = (blockIdx.x * 256 + threadIdx.x) >> 5;
    int lane = threadIdx.x & 31;
    if (n >= Nn) return;
    float r0 = 0.5f / g_z[n * 2];
    float r1 = 0.5f / g_z[n * 2 + 1];
    float y0 = 0.f, y1 = 0.f;
    const float* ac = &g_acc[(size_t)n * 128];
    #pragma unroll
    for (int r = 0; r < 2; ++r) {
        int dd = lane + 32 * r;
        float v = ac[dd] * r0 + ac[64 + dd] * r1 + gat_b[dd];
        v = v > 0.f ? v : 0.f;
        y0 += v * lin_w[dd];
        y1 += v * lin_w[64 + dd];
    }
    #pragma unroll
    for (int off = 16; off; off >>= 1) {
        y0 += __shfl_down_sync(0xffffffffu, y0, off);
        y1 += __shfl_down_sync(0xffffffffu, y1, off);
    }
    if (lane == 0) {
        out[n * 2]     = 1.f / (1.f + __expf(-(y0 + lin_b[0])));
        out[n * 2 + 1] = 1.f / (1.f + __expf(-(y1 + lin_b[1])));
    }
}

// ==================== launch =======================================
extern "C" void kernel_launch(void* const* d_in, const int* in_sizes, int n_in,
                              void* d_out, int out_size)
{
    const float* x       = (const float*)d_in[0];
    const int*   ei32    = (const int*)d_in[1];     // int32 view; probe decides layout
    const float* w_ih    = (const float*)d_in[2];
    const float* w_hh    = (const float*)d_in[3];
    const float* b_ih    = (const float*)d_in[4];
    const float* b_hh    = (const float*)d_in[5];
    const float* gat_w   = (const float*)d_in[6];
    const float* att_src = (const float*)d_in[7];
    const float* att_dst = (const float*)d_in[8];
    const float* gat_b   = (const float*)d_in[9];
    const float* lin_w   = (const float*)d_in[10];
    const float* lin_b   = (const float*)d_in[11];
    float*       out     = (float*)d_out;

    detect_kernel<<<1, 32>>>(ei32);
    lstm_kernel<<<Nn / NB, 256>>>(x, w_ih, w_hh, b_ih, b_hh);
    xform_kernel<<<Nn / 16, 256>>>(gat_w);
    attn_kernel<<<Nn / 8, 256>>>(att_src, att_dst);
    edge_sum_kernel<<<(ETOT + 7) / 8, 256>>>(ei32);
    final_kernel<<<Nn / 8, 256>>>(gat_b, lin_w, lin_b, out);
}

// round 10
// speedup vs baseline: 1.1935x; 1.0700x over previous
#include <cuda_runtime.h>
#include <cuda_fp16.h>
#include <math.h>

// Problem constants
#define Nn   100000
#define Tt   64
#define Ee   1000000
#define ETOT (Ee + Nn)    // edges + self loops
#define NB   32           // nodes per LSTM block
#define HW   36           // hsh row stride in 32-bit words
#define HS   (NB * HW)    // one h buffer in words

// -------- scratch (device globals; no allocations allowed) ----------
__device__ float   g_h[Nn * 64];     // LSTM final hidden
__device__ __half2 g_xh2[Nn * 64];   // GAT features, word p = (head p/32, dims 2p%64)
__device__ __half2 g_acc2[Nn * 64];  // weighted message accumulator (fp16x2)
__device__ float   g_asrc[Nn * 2];
__device__ float   g_adst[Nn * 2];
__device__ float   g_z[Nn * 2];      // segment sum (fp32)
__device__ int     g_estride;        // 1 if edge_index is int32, 2 if int64
__device__ int     g_eoff;           // offset (in int32 words) of dst row

// ==================== edge dtype probe =============================
__global__ void detect_kernel(const int* __restrict__ ei32)
{
    if (threadIdx.x == 0 && blockIdx.x == 0) {
        bool all0 = true;
        #pragma unroll
        for (int i = 1; i < 64; i += 2) all0 &= (ei32[i] == 0);
        g_estride = all0 ? 2 : 1;
        g_eoff    = all0 ? 2 * Ee : Ee;
    }
}

// ==================== helpers ======================================
__device__ __forceinline__ unsigned tanh2(unsigned x)
{
    unsigned y;
    asm("tanh.approx.f16x2 %0, %1;" : "=r"(y) : "r"(x));
    return y;
}
__device__ __forceinline__ __half2 u2h(unsigned u) { return *reinterpret_cast<__half2*>(&u); }
__device__ __forceinline__ unsigned h2u(__half2 h) { return *reinterpret_cast<unsigned*>(&h); }

// fp16x2 sigmoid: 0.5 + 0.5*tanh(0.5*x)
__device__ __forceinline__ __half2 sig2(unsigned u, __half2 half05)
{
    __half2 x = __hmul2(u2h(u), half05);
    return __hfma2(u2h(tanh2(h2u(x))), half05, half05);
}

__device__ __forceinline__ unsigned f2h2u(float a, float b)
{
    __half2 h = __floats2half2_rn(a, b);
    return *reinterpret_cast<unsigned*>(&h);
}

// m16n8k16, fp16 in / fp16 accum. D regs = 2x fp16x2.
__device__ __forceinline__ void mma_f16acc(unsigned& c0, unsigned& c1,
                                           unsigned a0, unsigned a1, unsigned a2, unsigned a3,
                                           unsigned b0, unsigned b1)
{
    asm("mma.sync.aligned.m16n8k16.row.col.f16.f16.f16.f16 "
        "{%0,%1}, {%2,%3,%4,%5}, {%6,%7}, {%0,%1};"
        : "+r"(c0), "+r"(c1)
        : "r"(a0), "r"(a1), "r"(a2), "r"(a3), "r"(b0), "r"(b1));
}

// ==================== LSTM (all-fp16, 32 nodes/block) ==============
// Unchanged from R9 (at legacy-HMMA throughput floor).
__global__ void __launch_bounds__(256, 2)
lstm_kernel(const float* __restrict__ x, const float* __restrict__ w_ih,
            const float* __restrict__ w_hh, const float* __restrict__ b_ih,
            const float* __restrict__ b_hh)
{
    __shared__ unsigned xsh[Tt * NB * 2];   // broadcast half2 per (t, n, d)
    __shared__ unsigned hsh[2 * HS];        // double-buffered h, fp16x2 words

    const int tid  = threadIdx.x;
    const int base = blockIdx.x * NB;
    const int wid  = tid >> 5, lane = tid & 31;
    const int grp  = lane >> 2, tig = lane & 3;

    for (int i = tid; i < NB * Tt * 2; i += 256) {
        int n = i >> 7;
        int r = i & 127;
        float v = x[(size_t)(base + n) * 128 + r];
        xsh[(r >> 1) * (NB * 2) + n * 2 + (r & 1)] = h2u(__float2half2_rn(v));
    }
    for (int i = tid; i < 2 * HS; i += 256) hsh[i] = 0u;

    const int j0 = wid * 8 + 2 * tig;

    unsigned bias2[4], wa2[4], wb2[4];
    #pragma unroll
    for (int q = 0; q < 4; ++q) {
        int g = q * 64 + j0;
        bias2[q] = f2h2u(b_ih[g] + b_hh[g], b_ih[g + 1] + b_hh[g + 1]);
        wa2[q]   = f2h2u(w_ih[g * 2],     w_ih[(g + 1) * 2]);
        wb2[q]   = f2h2u(w_ih[g * 2 + 1], w_ih[(g + 1) * 2 + 1]);
    }

    unsigned bf[4][4][2];
    #pragma unroll
    for (int q = 0; q < 4; ++q) {
        const float* wr = &w_hh[(size_t)(q * 64 + wid * 8 + grp) * 64];
        #pragma unroll
        for (int kt = 0; kt < 4; ++kt) {
            int k = kt * 16 + 2 * tig;
            bf[q][kt][0] = f2h2u(wr[k],     wr[k + 1]);
            bf[q][kt][1] = f2h2u(wr[k + 8], wr[k + 9]);
        }
    }

    const int rp[4] = { grp * HW + tig,        (grp + 8) * HW + tig,
                        (grp + 16) * HW + tig, (grp + 24) * HW + tig };
    const int sp[4] = { grp * HW + wid * 4 + tig,        (grp + 8) * HW + wid * 4 + tig,
                        (grp + 16) * HW + wid * 4 + tig, (grp + 24) * HW + wid * 4 + tig };

    const __half2 half05 = __float2half2_rn(0.5f);
    __half2 creg[4];
    #pragma unroll
    for (int r = 0; r < 4; ++r) creg[r] = __float2half2_rn(0.f);

    __syncthreads();

    for (int t = 0; t < Tt; ++t) {
        const unsigned* rb   = &hsh[(t & 1) * HS];
        unsigned*       wbuf = &hsh[((t + 1) & 1) * HS];

        unsigned xl[4], xh[4];
        #pragma unroll
        for (int m = 0; m < 4; ++m) {
            int n = grp + 8 * m;
            xl[m] = xsh[t * (NB * 2) + n * 2];
            xh[m] = xsh[t * (NB * 2) + n * 2 + 1];
        }
        unsigned c[4][4];
        #pragma unroll
        for (int q = 0; q < 4; ++q) {
            #pragma unroll
            for (int m = 0; m < 4; ++m)
                c[q][m] = h2u(__hfma2(u2h(wb2[q]), u2h(xh[m]),
                              __hfma2(u2h(wa2[q]), u2h(xl[m]), u2h(bias2[q]))));
        }
        #pragma unroll
        for (int kt = 0; kt < 4; ++kt) {
            unsigned a0 = rb[rp[0] + kt * 8];
            unsigned a1 = rb[rp[1] + kt * 8];
            unsigned a2 = rb[rp[0] + kt * 8 + 4];
            unsigned a3 = rb[rp[1] + kt * 8 + 4];
            unsigned a4 = rb[rp[2] + kt * 8];
            unsigned a5 = rb[rp[3] + kt * 8];
            unsigned a6 = rb[rp[2] + kt * 8 + 4];
            unsigned a7 = rb[rp[3] + kt * 8 + 4];
            #pragma unroll
            for (int q = 0; q < 4; ++q) {
                mma_f16acc(c[q][0], c[q][1], a0, a1, a2, a3,
                           bf[q][kt][0], bf[q][kt][1]);
                mma_f16acc(c[q][2], c[q][3], a4, a5, a6, a7,
                           bf[q][kt][0], bf[q][kt][1]);
            }
        }

        #pragma unroll
        for (int r = 0; r < 4; ++r) {
            __half2 i2 = sig2(c[0][r], half05);
            __half2 f2 = sig2(c[1][r], half05);
            __half2 g2 = u2h(tanh2(c[2][r]));
            __half2 o2 = sig2(c[3][r], half05);
            creg[r] = __hfma2(f2, creg[r], __hmul2(i2, g2));
            __half2 hh = __hmul2(o2, u2h(tanh2(h2u(creg[r]))));
            if (t == Tt - 1) {
                int row = grp + 8 * r;
                *(float2*)&g_h[(size_t)(base + row) * 64 + j0] =
                    make_float2(__low2float(hh), __high2float(hh));
            } else {
                wbuf[sp[r]] = h2u(hh);
            }
        }
        __syncthreads();
    }
}

// ==================== GAT: feature transform (fp16 out) ============
// Thread owns word p = (head, dim pair); 4 nodes of the 16-node tile.
__global__ void __launch_bounds__(256)
xform_kernel(const float* __restrict__ gat_w)
{
    __shared__ float gwt[64 * 128];   // gat_w transposed [k][hg]
    __shared__ float hs[16 * 64];     // 16 nodes
    const int tid  = threadIdx.x;
    const int base = blockIdx.x * 16;

    for (int i = tid; i < 128 * 64; i += 256) {
        int hg = i >> 6, k = i & 63;
        gwt[k * 128 + hg] = gat_w[i];
    }
    for (int i = tid; i < 16 * 64; i += 256) hs[i] = g_h[(size_t)base * 64 + i];
    __syncthreads();

    const int p = tid & 63, ng = tid >> 6;   // word p; nodes ng*4..ng*4+3
    float a0[4] = {0, 0, 0, 0}, a1[4] = {0, 0, 0, 0};
    #pragma unroll 4
    for (int k = 0; k < 64; ++k) {
        float w0 = gwt[k * 128 + 2 * p];
        float w1 = gwt[k * 128 + 2 * p + 1];
        #pragma unroll
        for (int i = 0; i < 4; ++i) {
            float h = hs[(ng * 4 + i) * 64 + k];
            a0[i] = fmaf(h, w0, a0[i]);
            a1[i] = fmaf(h, w1, a1[i]);
        }
    }
    #pragma unroll
    for (int i = 0; i < 4; ++i) {
        size_t n = base + ng * 4 + i;
        g_xh2[n * 64 + p]  = __floats2half2_rn(a0[i], a1[i]);
        g_acc2[n * 64 + p] = __float2half2_rn(0.f);
    }
}

// ==================== GAT: attention coefficients ==================
// One warp per node; lane handles word lane (head0) and 32+lane (head1).
__global__ void __launch_bounds__(256)
attn_kernel(const float* __restrict__ att_src, const float* __restrict__ att_dst)
{
    int n    = (blockIdx.x * 256 + threadIdx.x) >> 5;
    int lane = threadIdx.x & 31;
    if (n >= Nn) return;
    float2 x0 = __half22float2(g_xh2[(size_t)n * 64 + lane]);
    float2 x1 = __half22float2(g_xh2[(size_t)n * 64 + 32 + lane]);
    float2 as0 = ((const float2*)att_src)[lane];
    float2 as1 = ((const float2*)att_src)[32 + lane];
    float2 ad0 = ((const float2*)att_dst)[lane];
    float2 ad1 = ((const float2*)att_dst)[32 + lane];
    float ps0 = x0.x * as0.x + x0.y * as0.y;
    float ps1 = x1.x * as1.x + x1.y * as1.y;
    float pd0 = x0.x * ad0.x + x0.y * ad0.y;
    float pd1 = x1.x * ad1.x + x1.y * ad1.y;
    #pragma unroll
    for (int off = 16; off; off >>= 1) {
        ps0 += __shfl_down_sync(0xffffffffu, ps0, off);
        ps1 += __shfl_down_sync(0xffffffffu, ps1, off);
        pd0 += __shfl_down_sync(0xffffffffu, pd0, off);
        pd1 += __shfl_down_sync(0xffffffffu, pd1, off);
    }
    if (lane == 0) {
        g_asrc[n * 2]     = ps0;
        g_asrc[n * 2 + 1] = ps1;
        g_adst[n * 2]     = pd0;
        g_adst[n * 2 + 1] = pd1;
        g_z[n * 2]        = 0.f;
        g_z[n * 2 + 1]    = 0.f;
    }
}

// ==================== GAT: exp-sum + weighted messages (fp16) ======
// Logits are O(0.05): softmax without max-subtraction is exact-safe.
// Per edge-warp: 2 half2 gathers + 2 half2 atomics per lane.
__global__ void __launch_bounds__(256)
edge_sum_kernel(const int* __restrict__ ei32)
{
    int w    = (blockIdx.x * 256 + threadIdx.x) >> 5;
    int lane = threadIdx.x & 31;
    if (w >= ETOT) return;
    const int st = g_estride, of = g_eoff;
    int s, d;
    if (w < Ee) { s = ei32[(size_t)w * st]; d = ei32[(size_t)of + (size_t)w * st]; }
    else        { s = d = w - Ee; }
    float e0 = g_asrc[s * 2]     + g_adst[d * 2];
    float e1 = g_asrc[s * 2 + 1] + g_adst[d * 2 + 1];
    e0 = e0 > 0.f ? e0 : 0.2f * e0;
    e1 = e1 > 0.f ? e1 : 0.2f * e1;
    float w0 = __expf(e0);
    float w1 = __expf(e1);
    if (lane == 0) {
        atomicAdd(&g_z[d * 2],     w0);
        atomicAdd(&g_z[d * 2 + 1], w1);
    }
    __half2 c0 = __float2half2_rn(w0);
    __half2 c1 = __float2half2_rn(w1);
    __half2 x0 = g_xh2[(size_t)s * 64 + lane];
    __half2 x1 = g_xh2[(size_t)s * 64 + 32 + lane];
    atomicAdd(&g_acc2[(size_t)d * 64 + lane],      __hmul2(x0, c0));
    atomicAdd(&g_acc2[(size_t)d * 64 + 32 + lane], __hmul2(x1, c1));
}

// ==================== finalize: mean heads + relu + linear + sigmoid
__global__ void __launch_bounds__(256)
final_kernel(const float* __restrict__ gat_b, const float* __restrict__ lin_w,
             const float* __restrict__ lin_b, float* __restrict__ out)
{
    int n    = (blockIdx.x * 256 + threadIdx.x) >> 5;
    int lane = threadIdx.x & 31;
    if (n >= Nn) return;
    float r0 = 0.5f / g_z[n * 2];
    float r1 = 0.5f / g_z[n * 2 + 1];
    float2 a0 = __half22float2(g_acc2[(size_t)n * 64 + lane]);        // head0, dims 2l,2l+1
    float2 a1 = __half22float2(g_acc2[(size_t)n * 64 + 32 + lane]);   // head1, same dims
    float2 gb = ((const float2*)gat_b)[lane];
    float v0 = a0.x * r0 + a1.x * r1 + gb.x;
    float v1 = a0.y * r0 + a1.y * r1 + gb.y;
    v0 = v0 > 0.f ? v0 : 0.f;
    v1 = v1 > 0.f ? v1 : 0.f;
    float2 l0 = ((const float2*)lin_w)[lane];        // row0
    float2 l1 = ((const float2*)lin_w)[32 + lane];   // row1
    float y0 = v0 * l0.x + v1 * l0.y;
    float y1 = v0 * l1.x + v1 * l1.y;
    #pragma unroll
    for (int off = 16; off; off >>= 1) {
        y0 += __shfl_down_sync(0xffffffffu, y0, off);
        y1 += __shfl_down_sync(0xffffffffu, y1, off);
    }
    if (lane == 0) {
        out[n * 2]     = 1.f / (1.f + __expf(-(y0 + lin_b[0])));
        out[n * 2 + 1] = 1.f / (1.f + __expf(-(y1 + lin_b[1])));
    }
}

// ==================== launch =======================================
extern "C" void kernel_launch(void* const* d_in, const int* in_sizes, int n_in,
                              void* d_out, int out_size)
{
    const float* x       = (const float*)d_in[0];
    const int*   ei32    = (const int*)d_in[1];     // int32 view; probe decides layout
    const float* w_ih    = (const float*)d_in[2];
    const float* w_hh    = (const float*)d_in[3];
    const float* b_ih    = (const float*)d_in[4];
    const float* b_hh    = (const float*)d_in[5];
    const float* gat_w   = (const float*)d_in[6];
    const float* att_src = (const float*)d_in[7];
    const float* att_dst = (const float*)d_in[8];
    const float* gat_b   = (const float*)d_in[9];
    const float* lin_w   = (const float*)d_in[10];
    const float* lin_b   = (const float*)d_in[11];
    float*       out     = (float*)d_out;

    detect_kernel<<<1, 32>>>(ei32);
    lstm_kernel<<<Nn / NB, 256>>>(x, w_ih, w_hh, b_ih, b_hh);
    xform_kernel<<<Nn / 16, 256>>>(gat_w);
    attn_kernel<<<Nn / 8, 256>>>(att_src, att_dst);
    edge_sum_kernel<<<(ETOT + 7) / 8, 256>>>(ei32);
    final_kernel<<<Nn / 8, 256>>>(gat_b, lin_w, lin_b, out);
}